// round 9
// baseline (speedup 1.0000x reference)
#include <cuda_runtime.h>
#include <cuda_fp16.h>
#include <math.h>

#define Nn 12288
#define Ff 256
#define Hh 64
#define Cc 16
#define MAXDEG 256
#define ALPHAc 0.3f
#define LN_EPS 1e-5f

#define GEMM_BLOCKS 384
#define CSR_BLOCKS  1536

// ---------------- scratch ----------------
__device__ int    g_colidx[Nn * MAXDEG];
__device__ int    g_deg[Nn];
__device__ float  g_dinv[Nn];
__device__ float  g_rowsum[Nn];
__device__ float  g_h0[Nn * Hh];
__device__ __half g_hsA[Nn * Hh];
__device__ __half g_hsB[Nn * Hh];
__device__ float  g_gm[Nn * Cc];
__device__ __half g_gs[Nn * Cc];
__device__ double g_acc[3];

// ---- CSR compaction of one float4 group (warp-wide) ----
__device__ __forceinline__ int compact4(float4 v, int col, int base, int cnt, unsigned lt) {
    int n0 = (v.x != 0.f), n1 = (v.y != 0.f), n2 = (v.z != 0.f), n3 = (v.w != 0.f);
    unsigned b0 = __ballot_sync(0xffffffffu, n0);
    unsigned b1 = __ballot_sync(0xffffffffu, n1);
    unsigned b2 = __ballot_sync(0xffffffffu, n2);
    unsigned b3 = __ballot_sync(0xffffffffu, n3);
    int t0 = __popc(b0), t1 = __popc(b1), t2 = __popc(b2);
    if (n0) g_colidx[base + cnt + __popc(b0 & lt)] = col;
    if (n1) g_colidx[base + cnt + t0 + __popc(b1 & lt)] = col + 1;
    if (n2) g_colidx[base + cnt + t0 + t1 + __popc(b2 & lt)] = col + 2;
    if (n3) g_colidx[base + cnt + t0 + t1 + t2 + __popc(b3 & lt)] = col + 3;
    return cnt + t0 + t1 + t2 + __popc(b3);
}

// ======= fused front: blocks [0,384) = x@W_in GEMM ; blocks [384,1920) = CSR build =======
__global__ __launch_bounds__(256) void k_front(const float* __restrict__ adj,
                                               const float* __restrict__ x,
                                               const float* __restrict__ Win,
                                               const float* __restrict__ bin) {
    __shared__ float xs[32][33];
    __shared__ float Ws[32][64];
    int tid = threadIdx.x;

    if (blockIdx.x < GEMM_BLOCKS) {
        if (blockIdx.x == 0 && tid < 3) g_acc[tid] = 0.0;
        int tx = tid & 15, ty = tid >> 4;
        int row0 = blockIdx.x * 32;
        float acc[2][4];
        #pragma unroll
        for (int i = 0; i < 2; i++)
            #pragma unroll
            for (int jj = 0; jj < 4; jj++) acc[i][jj] = 0.f;

        const float* xBase = x + (size_t)row0 * Ff;
        int lr = tid >> 3, lk = (tid & 7) * 4;
        for (int kc = 0; kc < Ff; kc += 32) {
            float4 v = *(const float4*)(xBase + (size_t)lr * Ff + kc + lk);
            xs[lr][lk + 0] = v.x; xs[lr][lk + 1] = v.y;
            xs[lr][lk + 2] = v.z; xs[lr][lk + 3] = v.w;
            #pragma unroll
            for (int l = 0; l < 2; l++) {
                int q = tid + l * 256;
                int k = q >> 4, c4 = q & 15;
                *(float4*)&Ws[k][c4 * 4] =
                    ((const float4*)(Win + (size_t)(kc + k) * Hh))[c4];
            }
            __syncthreads();
            #pragma unroll
            for (int kk = 0; kk < 32; kk++) {
                float4 b = *(const float4*)&Ws[kk][tx * 4];
                float a0 = xs[ty * 2 + 0][kk];
                float a1 = xs[ty * 2 + 1][kk];
                acc[0][0] = fmaf(a0, b.x, acc[0][0]); acc[0][1] = fmaf(a0, b.y, acc[0][1]);
                acc[0][2] = fmaf(a0, b.z, acc[0][2]); acc[0][3] = fmaf(a0, b.w, acc[0][3]);
                acc[1][0] = fmaf(a1, b.x, acc[1][0]); acc[1][1] = fmaf(a1, b.y, acc[1][1]);
                acc[1][2] = fmaf(a1, b.z, acc[1][2]); acc[1][3] = fmaf(a1, b.w, acc[1][3]);
            }
            __syncthreads();
        }
        float4 bb = ((const float4*)bin)[tx];
        #pragma unroll
        for (int i = 0; i < 2; i++) {
            int row = row0 + ty * 2 + i;
            float4 v;
            v.x = acc[i][0] + bb.x; v.y = acc[i][1] + bb.y;
            v.z = acc[i][2] + bb.z; v.w = acc[i][3] + bb.w;
            ((float4*)g_h0)[row * 16 + tx] = v;
        }
    } else {
        // ---- CSR build: warp per row, 8x unrolled streaming (MLP 8) ----
        int warp = (blockIdx.x - GEMM_BLOCKS) * 8 + (tid >> 5);
        int lane = tid & 31;
        unsigned lt = (1u << lane) - 1u;
        const float4* arow = (const float4*)(adj + (size_t)warp * Nn);
        int cnt = 0;
        int base = warp * MAXDEG;
        #pragma unroll 1
        for (int c0 = 0; c0 < Nn / 4; c0 += 256) {
            float4 v0 = __ldcs(&arow[c0 +   0 + lane]);
            float4 v1 = __ldcs(&arow[c0 +  32 + lane]);
            float4 v2 = __ldcs(&arow[c0 +  64 + lane]);
            float4 v3 = __ldcs(&arow[c0 +  96 + lane]);
            float4 v4 = __ldcs(&arow[c0 + 128 + lane]);
            float4 v5 = __ldcs(&arow[c0 + 160 + lane]);
            float4 v6 = __ldcs(&arow[c0 + 192 + lane]);
            float4 v7 = __ldcs(&arow[c0 + 224 + lane]);
            cnt = compact4(v0, (c0 +   0 + lane) * 4, base, cnt, lt);
            cnt = compact4(v1, (c0 +  32 + lane) * 4, base, cnt, lt);
            cnt = compact4(v2, (c0 +  64 + lane) * 4, base, cnt, lt);
            cnt = compact4(v3, (c0 +  96 + lane) * 4, base, cnt, lt);
            cnt = compact4(v4, (c0 + 128 + lane) * 4, base, cnt, lt);
            cnt = compact4(v5, (c0 + 160 + lane) * 4, base, cnt, lt);
            cnt = compact4(v6, (c0 + 192 + lane) * 4, base, cnt, lt);
            cnt = compact4(v7, (c0 + 224 + lane) * 4, base, cnt, lt);
        }
        if (lane == 0) {
            g_deg[warp]  = cnt;
            g_dinv[warp] = rsqrtf((float)cnt + 1.0f);
        }
    }
}

// ======= mid: rowsum + Wsum + hsA = fp16(dinv*h0)  (one warp per row) =======
__global__ void k_mid() {
    int row = (blockIdx.x * blockDim.x + threadIdx.x) >> 5;
    if (row >= Nn) return;
    int lane = threadIdx.x & 31;
    int deg = g_deg[row];
    const int* ci = g_colidx + row * MAXDEG;
    float s = 0.f;
    for (int e = lane; e < deg; e += 32) s += g_dinv[ci[e]];
    #pragma unroll
    for (int d = 16; d; d >>= 1) s += __shfl_xor_sync(0xffffffffu, s, d);
    float du = g_dinv[row];
    if (lane == 0) {
        float rs = du * (du + s);
        g_rowsum[row] = rs;
        atomicAdd(&g_acc[2], (double)rs);
    }
    float h0a = g_h0[row * Hh + lane];
    float h0b = g_h0[row * Hh + lane + 32];
    g_hsA[row * Hh + lane]      = __float2half_rn(du * h0a);
    g_hsA[row * Hh + lane + 32] = __float2half_rn(du * h0b);
}

// ---- shared gather helper: 16 threads/row, uint2 fp16, MLP-8 into 4 acc chains ----
__device__ __forceinline__ float4 gather_row(const uint2* hs2, int row, int j) {
    float2 f0, f1;
    {
        uint2 s0 = __ldg(&hs2[row * 16 + j]);
        f0 = __half22float2(*(__half2*)&s0.x);
        f1 = __half22float2(*(__half2*)&s0.y);
    }
    float ax = f0.x, ay = f0.y, az = f1.x, aw = f1.y;
    float bx = 0.f, by = 0.f, bz = 0.f, bw = 0.f;
    float cx = 0.f, cy = 0.f, cz = 0.f, cw = 0.f;
    float ex_ = 0.f, ey_ = 0.f, ez_ = 0.f, ew_ = 0.f;
    int deg = g_deg[row];
    const int* ci = g_colidx + row * MAXDEG;
    int e = 0;
    #pragma unroll 1
    for (; e + 8 <= deg; e += 8) {
        uint2 u0 = __ldg(&hs2[__ldg(&ci[e + 0]) * 16 + j]);
        uint2 u1 = __ldg(&hs2[__ldg(&ci[e + 1]) * 16 + j]);
        uint2 u2 = __ldg(&hs2[__ldg(&ci[e + 2]) * 16 + j]);
        uint2 u3 = __ldg(&hs2[__ldg(&ci[e + 3]) * 16 + j]);
        uint2 u4 = __ldg(&hs2[__ldg(&ci[e + 4]) * 16 + j]);
        uint2 u5 = __ldg(&hs2[__ldg(&ci[e + 5]) * 16 + j]);
        uint2 u6 = __ldg(&hs2[__ldg(&ci[e + 6]) * 16 + j]);
        uint2 u7 = __ldg(&hs2[__ldg(&ci[e + 7]) * 16 + j]);
        float2 g;
        g = __half22float2(*(__half2*)&u0.x); ax += g.x; ay += g.y;
        g = __half22float2(*(__half2*)&u0.y); az += g.x; aw += g.y;
        g = __half22float2(*(__half2*)&u1.x); bx += g.x; by += g.y;
        g = __half22float2(*(__half2*)&u1.y); bz += g.x; bw += g.y;
        g = __half22float2(*(__half2*)&u2.x); cx += g.x; cy += g.y;
        g = __half22float2(*(__half2*)&u2.y); cz += g.x; cw += g.y;
        g = __half22float2(*(__half2*)&u3.x); ex_ += g.x; ey_ += g.y;
        g = __half22float2(*(__half2*)&u3.y); ez_ += g.x; ew_ += g.y;
        g = __half22float2(*(__half2*)&u4.x); ax += g.x; ay += g.y;
        g = __half22float2(*(__half2*)&u4.y); az += g.x; aw += g.y;
        g = __half22float2(*(__half2*)&u5.x); bx += g.x; by += g.y;
        g = __half22float2(*(__half2*)&u5.y); bz += g.x; bw += g.y;
        g = __half22float2(*(__half2*)&u6.x); cx += g.x; cy += g.y;
        g = __half22float2(*(__half2*)&u6.y); cz += g.x; cw += g.y;
        g = __half22float2(*(__half2*)&u7.x); ex_ += g.x; ey_ += g.y;
        g = __half22float2(*(__half2*)&u7.y); ez_ += g.x; ew_ += g.y;
    }
    for (; e + 4 <= deg; e += 4) {
        uint2 u0 = __ldg(&hs2[__ldg(&ci[e + 0]) * 16 + j]);
        uint2 u1 = __ldg(&hs2[__ldg(&ci[e + 1]) * 16 + j]);
        uint2 u2 = __ldg(&hs2[__ldg(&ci[e + 2]) * 16 + j]);
        uint2 u3 = __ldg(&hs2[__ldg(&ci[e + 3]) * 16 + j]);
        float2 g;
        g = __half22float2(*(__half2*)&u0.x); ax += g.x; ay += g.y;
        g = __half22float2(*(__half2*)&u0.y); az += g.x; aw += g.y;
        g = __half22float2(*(__half2*)&u1.x); bx += g.x; by += g.y;
        g = __half22float2(*(__half2*)&u1.y); bz += g.x; bw += g.y;
        g = __half22float2(*(__half2*)&u2.x); cx += g.x; cy += g.y;
        g = __half22float2(*(__half2*)&u2.y); cz += g.x; cw += g.y;
        g = __half22float2(*(__half2*)&u3.x); ex_ += g.x; ey_ += g.y;
        g = __half22float2(*(__half2*)&u3.y); ez_ += g.x; ew_ += g.y;
    }
    for (; e < deg; e++) {
        uint2 u0 = __ldg(&hs2[__ldg(&ci[e]) * 16 + j]);
        float2 g;
        g = __half22float2(*(__half2*)&u0.x); ax += g.x; ay += g.y;
        g = __half22float2(*(__half2*)&u0.y); az += g.x; aw += g.y;
    }
    float4 o;
    o.x = ax + bx + cx + ex_;
    o.y = ay + by + cy + ey_;
    o.z = az + bz + cz + ez_;
    o.w = aw + bw + cw + ew_;
    return o;
}

// ======= LN layers: 16 rows/block, 16 thr/row, grid = Nn/16 =======
__global__ __launch_bounds__(256) void k_layer(const __half* __restrict__ hs_in,
                                               __half* __restrict__ hs_out,
                                               const float* __restrict__ Wc,
                                               const float* __restrict__ lng,
                                               const float* __restrict__ lnb,
                                               float beta) {
    __shared__ float sW[Hh * Hh];
    __shared__ float sHm[16][Hh + 4];   // stride 272 B: 16B-aligned rows
    for (int i = threadIdx.x; i < Hh * Hh / 4; i += 256)
        ((float4*)sW)[i] = ((const float4*)Wc)[i];
    int r = threadIdx.x >> 4, j = threadIdx.x & 15;
    int row = blockIdx.x * 16 + r;
    float du = g_dinv[row];

    float4 a = gather_row((const uint2*)hs_in, row, j);

    float4 h0v = ((const float4*)g_h0)[row * 16 + j];
    float c1 = (1.f - ALPHAc) * du;
    float4 hm;
    hm.x = fmaf(c1, a.x, ALPHAc * h0v.x);
    hm.y = fmaf(c1, a.y, ALPHAc * h0v.y);
    hm.z = fmaf(c1, a.z, ALPHAc * h0v.z);
    hm.w = fmaf(c1, a.w, ALPHAc * h0v.w);
    *(float4*)&sHm[r][4 * j] = hm;
    __syncthreads();

    float4 t = make_float4(0.f, 0.f, 0.f, 0.f);
    const float* hmrow = sHm[r];
    #pragma unroll
    for (int k = 0; k < Hh; k++) {
        float hk = hmrow[k];
        float4 w = *(const float4*)&sW[k * Hh + 4 * j];
        t.x = fmaf(hk, w.x, t.x);
        t.y = fmaf(hk, w.y, t.y);
        t.z = fmaf(hk, w.z, t.z);
        t.w = fmaf(hk, w.w, t.w);
    }
    float4 v;
    v.x = fmaf(beta, t.x - hm.x, hm.x);
    v.y = fmaf(beta, t.y - hm.y, hm.y);
    v.z = fmaf(beta, t.z - hm.z, hm.z);
    v.w = fmaf(beta, t.w - hm.w, hm.w);

    // ReLU + LN
    v.x = fmaxf(v.x, 0.f); v.y = fmaxf(v.y, 0.f);
    v.z = fmaxf(v.z, 0.f); v.w = fmaxf(v.w, 0.f);
    float s = v.x + v.y + v.z + v.w;
    #pragma unroll
    for (int d = 8; d; d >>= 1) s += __shfl_xor_sync(0xffffffffu, s, d);
    float mu = s * (1.f / 64.f);
    float dx = v.x - mu, dy = v.y - mu, dz = v.z - mu, dw = v.w - mu;
    float q = dx * dx + dy * dy + dz * dz + dw * dw;
    #pragma unroll
    for (int d = 8; d; d >>= 1) q += __shfl_xor_sync(0xffffffffu, q, d);
    float rstd = rsqrtf(q * (1.f / 64.f) + LN_EPS);
    float4 gg = ((const float4*)lng)[j];
    float4 bb = ((const float4*)lnb)[j];
    v.x = fmaf(dx * rstd, gg.x, bb.x);
    v.y = fmaf(dy * rstd, gg.y, bb.y);
    v.z = fmaf(dz * rstd, gg.z, bb.z);
    v.w = fmaf(dw * rstd, gg.w, bb.w);
    __half2 p0 = __floats2half2_rn(du * v.x, du * v.y);
    __half2 p1 = __floats2half2_rn(du * v.z, du * v.w);
    uint2 o;
    o.x = *(unsigned*)&p0; o.y = *(unsigned*)&p1;
    ((uint2*)hs_out)[row * 16 + j] = o;
}

// ======= final layer fused with output head: GEMM + out + log_softmax + Dirichlet =======
__global__ __launch_bounds__(256) void k_layer_last(const __half* __restrict__ hs_in,
                                                    const float* __restrict__ Wc,
                                                    const float* __restrict__ Wout,
                                                    const float* __restrict__ bout,
                                                    float beta,
                                                    float* __restrict__ dout) {
    __shared__ float sW[Hh * Hh];
    __shared__ float sWo[Hh * Cc];
    __shared__ float sHm[16][Hh + 4];
    for (int i = threadIdx.x; i < Hh * Hh / 4; i += 256)
        ((float4*)sW)[i] = ((const float4*)Wc)[i];
    if (threadIdx.x < Hh * Cc / 4)
        ((float4*)sWo)[threadIdx.x] = ((const float4*)Wout)[threadIdx.x];
    int r = threadIdx.x >> 4, j = threadIdx.x & 15;
    int row = blockIdx.x * 16 + r;
    float du = g_dinv[row];

    float4 a = gather_row((const uint2*)hs_in, row, j);

    float4 h0v = ((const float4*)g_h0)[row * 16 + j];
    float c1 = (1.f - ALPHAc) * du;
    float4 hm;
    hm.x = fmaf(c1, a.x, ALPHAc * h0v.x);
    hm.y = fmaf(c1, a.y, ALPHAc * h0v.y);
    hm.z = fmaf(c1, a.z, ALPHAc * h0v.z);
    hm.w = fmaf(c1, a.w, ALPHAc * h0v.w);
    *(float4*)&sHm[r][4 * j] = hm;
    __syncthreads();

    float4 t = make_float4(0.f, 0.f, 0.f, 0.f);
    const float* hmrow = sHm[r];
    #pragma unroll
    for (int k = 0; k < Hh; k++) {
        float hk = hmrow[k];
        float4 w = *(const float4*)&sW[k * Hh + 4 * j];
        t.x = fmaf(hk, w.x, t.x);
        t.y = fmaf(hk, w.y, t.y);
        t.z = fmaf(hk, w.z, t.z);
        t.w = fmaf(hk, w.w, t.w);
    }
    float4 v;
    v.x = fmaf(beta, t.x - hm.x, hm.x);
    v.y = fmaf(beta, t.y - hm.y, hm.y);
    v.z = fmaf(beta, t.z - hm.z, hm.z);
    v.w = fmaf(beta, t.w - hm.w, hm.w);

    __syncwarp();
    *(float4*)&sHm[r][4 * j] = v;
    __syncwarp();

    // output head: thread j = class j
    const float* vr = sHm[r];
    float o = bout[j];
    #pragma unroll
    for (int k = 0; k < Hh; k++) o = fmaf(vr[k], sWo[k * Cc + j], o);
    dout[row * Cc + j] = o;
    float m = o;
    #pragma unroll
    for (int d = 1; d < 16; d <<= 1) m = fmaxf(m, __shfl_xor_sync(0xffffffffu, m, d));
    float ex = expf(o - m);
    float se = ex;
    #pragma unroll
    for (int d = 1; d < 16; d <<= 1) se += __shfl_xor_sync(0xffffffffu, se, d);
    dout[Nn * Cc + row * Cc + j] = o - m - logf(se);

    float gv = fmaxf(o, 0.f) * rsqrtf((float)g_deg[row] + 2.0f);
    g_gm[row * Cc + j] = gv;
    g_gs[row * Cc + j] = __float2half_rn(du * gv);
    float s = gv * gv;
    #pragma unroll
    for (int d = 1; d < 16; d <<= 1) s += __shfl_xor_sync(0xffffffffu, s, d);
    if (j == 0) atomicAdd(&g_acc[0], (double)(g_rowsum[row] * s));
}

// ---- term2 = sum_u (W@g)_u . g_u   (8 threads/row, fp16 gather) ----
__global__ void k_wg() {
    int row = blockIdx.x * 32 + (threadIdx.x >> 3);
    int q = threadIdx.x & 7;
    const unsigned* gs2 = (const unsigned*)g_gs;
    float ax, ay;
    {
        float2 f = __half22float2(*(const __half2*)&gs2[row * 8 + q]);
        ax = f.x; ay = f.y;
    }
    float bx = 0.f, by = 0.f, cx = 0.f, cy = 0.f, dx = 0.f, dy = 0.f;
    int deg = g_deg[row];
    const int* ci = g_colidx + row * MAXDEG;
    int e = 0;
    #pragma unroll 1
    for (; e + 4 <= deg; e += 4) {
        unsigned u0 = __ldg(&gs2[__ldg(&ci[e])     * 8 + q]);
        unsigned u1 = __ldg(&gs2[__ldg(&ci[e + 1]) * 8 + q]);
        unsigned u2 = __ldg(&gs2[__ldg(&ci[e + 2]) * 8 + q]);
        unsigned u3 = __ldg(&gs2[__ldg(&ci[e + 3]) * 8 + q]);
        float2 f;
        f = __half22float2(*(__half2*)&u0); ax += f.x; ay += f.y;
        f = __half22float2(*(__half2*)&u1); bx += f.x; by += f.y;
        f = __half22float2(*(__half2*)&u2); cx += f.x; cy += f.y;
        f = __half22float2(*(__half2*)&u3); dx += f.x; dy += f.y;
    }
    for (; e < deg; e++) {
        float2 f = __half22float2(*(const __half2*)&gs2[__ldg(&ci[e]) * 8 + q]);
        ax += f.x; ay += f.y;
    }
    ax += bx + cx + dx; ay += by + cy + dy;
    float2 gu = ((const float2*)g_gm)[row * 8 + q];
    float dot = ax * gu.x + ay * gu.y;
    dot += __shfl_xor_sync(0xffffffffu, dot, 1);
    dot += __shfl_xor_sync(0xffffffffu, dot, 2);
    dot += __shfl_xor_sync(0xffffffffu, dot, 4);
    if (q == 0) atomicAdd(&g_acc[1], (double)(g_dinv[row] * dot));
}

__global__ void k_fin(float* __restrict__ dout) {
    dout[2 * Nn * Cc] = (float)((g_acc[0] - g_acc[1]) / g_acc[2]);
}

// ---------------- launch ----------------
extern "C" void kernel_launch(void* const* d_in, const int* in_sizes, int n_in,
                              void* d_out, int out_size) {
    const float* x    = (const float*)d_in[0];
    const float* adj  = (const float*)d_in[1];
    const float* Win  = (const float*)d_in[2];
    const float* bin  = (const float*)d_in[3];
    const float* Wcv  = (const float*)d_in[4];
    const float* lng  = (const float*)d_in[5];
    const float* lnb  = (const float*)d_in[6];
    const float* Wout = (const float*)d_in[7];
    const float* bout = (const float*)d_in[8];
    float* out = (float*)d_out;

    k_front<<<GEMM_BLOCKS + CSR_BLOCKS, 256>>>(adj, x, Win, bin);
    k_mid<<<Nn / 8, 256>>>();

    void* hsA_p = nullptr; void* hsB_p = nullptr;
    cudaGetSymbolAddress(&hsA_p, g_hsA);
    cudaGetSymbolAddress(&hsB_p, g_hsB);
    __half* hsA = (__half*)hsA_p;
    __half* hsB = (__half*)hsB_p;

    const float betas[4] = {0.26236426446749106f, 0.13976194237515863f,
                            0.09531017980432486f, 0.07232066157962608f};
    k_layer<<<Nn / 16, 256>>>(hsA, hsB, Wcv + 0 * Hh * Hh, lng + 0 * Hh, lnb + 0 * Hh, betas[0]);
    k_layer<<<Nn / 16, 256>>>(hsB, hsA, Wcv + 1 * Hh * Hh, lng + 1 * Hh, lnb + 1 * Hh, betas[1]);
    k_layer<<<Nn / 16, 256>>>(hsA, hsB, Wcv + 2 * Hh * Hh, lng + 2 * Hh, lnb + 2 * Hh, betas[2]);
    k_layer_last<<<Nn / 16, 256>>>(hsB, Wcv + 3 * Hh * Hh, Wout, bout, betas[3], out);

    k_wg<<<Nn / 32, 256>>>();
    k_fin<<<1, 1>>>(out);
}

// round 10
// speedup vs baseline: 1.1753x; 1.1753x over previous
#include <cuda_runtime.h>
#include <cuda_fp16.h>
#include <math.h>

#define Nn 12288
#define Ff 256
#define Hh 64
#define Cc 16
#define MAXDEG 256
#define ALPHAc 0.3f
#define LN_EPS 1e-5f

#define GEMM_BLOCKS 384
#define CSR_BLOCKS  1536

// ---------------- scratch ----------------
__device__ int    g_colidx[Nn * MAXDEG];
__device__ int    g_deg[Nn];
__device__ float  g_dinv[Nn];
__device__ float  g_rowsum[Nn];
__device__ float  g_h0[Nn * Hh];
__device__ __half g_hsA[Nn * Hh];
__device__ __half g_hsB[Nn * Hh];
__device__ float  g_gm[Nn * Cc];
__device__ __half g_gs[Nn * Cc];
__device__ double g_acc[3];

// ---- CSR compaction of one uint4 group (warp-wide); adjacency is exactly 0.0/1.0
//      so integer !=0 compares are equivalent to float !=0 ----
__device__ __forceinline__ int compact4u(uint4 v, int col, int base, int cnt, unsigned lt) {
    int n0 = (v.x != 0u), n1 = (v.y != 0u), n2 = (v.z != 0u), n3 = (v.w != 0u);
    unsigned b0 = __ballot_sync(0xffffffffu, n0);
    unsigned b1 = __ballot_sync(0xffffffffu, n1);
    unsigned b2 = __ballot_sync(0xffffffffu, n2);
    unsigned b3 = __ballot_sync(0xffffffffu, n3);
    int t0 = __popc(b0), t1 = __popc(b1), t2 = __popc(b2);
    if (n0) g_colidx[base + cnt + __popc(b0 & lt)] = col;
    if (n1) g_colidx[base + cnt + t0 + __popc(b1 & lt)] = col + 1;
    if (n2) g_colidx[base + cnt + t0 + t1 + __popc(b2 & lt)] = col + 2;
    if (n3) g_colidx[base + cnt + t0 + t1 + t2 + __popc(b3 & lt)] = col + 3;
    return cnt + t0 + t1 + t2 + __popc(b3);
}

// ======= fused front: blocks [0,384) = x@W_in GEMM ; blocks [384,1920) = CSR build =======
__global__ __launch_bounds__(256) void k_front(const float* __restrict__ adj,
                                               const float* __restrict__ x,
                                               const float* __restrict__ Win,
                                               const float* __restrict__ bin) {
    __shared__ float xs[32][33];
    __shared__ float Ws[32][64];
    int tid = threadIdx.x;

    if (blockIdx.x < GEMM_BLOCKS) {
        if (blockIdx.x == 0 && tid < 3) g_acc[tid] = 0.0;
        int tx = tid & 15, ty = tid >> 4;
        int row0 = blockIdx.x * 32;
        float acc[2][4];
        #pragma unroll
        for (int i = 0; i < 2; i++)
            #pragma unroll
            for (int jj = 0; jj < 4; jj++) acc[i][jj] = 0.f;

        const float* xBase = x + (size_t)row0 * Ff;
        int lr = tid >> 3, lk = (tid & 7) * 4;
        for (int kc = 0; kc < Ff; kc += 32) {
            float4 v = *(const float4*)(xBase + (size_t)lr * Ff + kc + lk);
            xs[lr][lk + 0] = v.x; xs[lr][lk + 1] = v.y;
            xs[lr][lk + 2] = v.z; xs[lr][lk + 3] = v.w;
            #pragma unroll
            for (int l = 0; l < 2; l++) {
                int q = tid + l * 256;
                int k = q >> 4, c4 = q & 15;
                *(float4*)&Ws[k][c4 * 4] =
                    ((const float4*)(Win + (size_t)(kc + k) * Hh))[c4];
            }
            __syncthreads();
            #pragma unroll
            for (int kk = 0; kk < 32; kk++) {
                float4 b = *(const float4*)&Ws[kk][tx * 4];
                float a0 = xs[ty * 2 + 0][kk];
                float a1 = xs[ty * 2 + 1][kk];
                acc[0][0] = fmaf(a0, b.x, acc[0][0]); acc[0][1] = fmaf(a0, b.y, acc[0][1]);
                acc[0][2] = fmaf(a0, b.z, acc[0][2]); acc[0][3] = fmaf(a0, b.w, acc[0][3]);
                acc[1][0] = fmaf(a1, b.x, acc[1][0]); acc[1][1] = fmaf(a1, b.y, acc[1][1]);
                acc[1][2] = fmaf(a1, b.z, acc[1][2]); acc[1][3] = fmaf(a1, b.w, acc[1][3]);
            }
            __syncthreads();
        }
        float4 bb = ((const float4*)bin)[tx];
        #pragma unroll
        for (int i = 0; i < 2; i++) {
            int row = row0 + ty * 2 + i;
            float4 v;
            v.x = acc[i][0] + bb.x; v.y = acc[i][1] + bb.y;
            v.z = acc[i][2] + bb.z; v.w = acc[i][3] + bb.w;
            ((float4*)g_h0)[row * 16 + tx] = v;
        }
    } else {
        // ---- CSR build: warp per row, MLP-4 streaming, all-zero warp-group skip ----
        int warp = (blockIdx.x - GEMM_BLOCKS) * 8 + (tid >> 5);
        int lane = tid & 31;
        unsigned lt = (1u << lane) - 1u;
        const uint4* arow = (const uint4*)(adj + (size_t)warp * Nn);
        int cnt = 0;
        int base = warp * MAXDEG;
        #pragma unroll 1
        for (int c0 = 0; c0 < Nn / 4; c0 += 128) {
            uint4 v0 = __ldcs(&arow[c0 +  0 + lane]);
            uint4 v1 = __ldcs(&arow[c0 + 32 + lane]);
            uint4 v2 = __ldcs(&arow[c0 + 64 + lane]);
            uint4 v3 = __ldcs(&arow[c0 + 96 + lane]);
            unsigned nz0 = (v0.x | v0.y) | (v0.z | v0.w);
            unsigned nz1 = (v1.x | v1.y) | (v1.z | v1.w);
            unsigned nz2 = (v2.x | v2.y) | (v2.z | v2.w);
            unsigned nz3 = (v3.x | v3.y) | (v3.z | v3.w);
            unsigned a0 = __ballot_sync(0xffffffffu, nz0 != 0u);
            unsigned a1 = __ballot_sync(0xffffffffu, nz1 != 0u);
            unsigned a2 = __ballot_sync(0xffffffffu, nz2 != 0u);
            unsigned a3 = __ballot_sync(0xffffffffu, nz3 != 0u);
            if (a0) cnt = compact4u(v0, (c0 +  0 + lane) * 4, base, cnt, lt);
            if (a1) cnt = compact4u(v1, (c0 + 32 + lane) * 4, base, cnt, lt);
            if (a2) cnt = compact4u(v2, (c0 + 64 + lane) * 4, base, cnt, lt);
            if (a3) cnt = compact4u(v3, (c0 + 96 + lane) * 4, base, cnt, lt);
        }
        if (lane == 0) {
            g_deg[warp]  = cnt;
            g_dinv[warp] = rsqrtf((float)cnt + 1.0f);
        }
    }
}

// ======= mid: rowsum + Wsum + hsA = fp16(dinv*h0)  (one warp per row) =======
__global__ void k_mid() {
    int row = (blockIdx.x * blockDim.x + threadIdx.x) >> 5;
    if (row >= Nn) return;
    int lane = threadIdx.x & 31;
    int deg = g_deg[row];
    const int* ci = g_colidx + row * MAXDEG;
    float s = 0.f;
    for (int e = lane; e < deg; e += 32) s += g_dinv[ci[e]];
    #pragma unroll
    for (int d = 16; d; d >>= 1) s += __shfl_xor_sync(0xffffffffu, s, d);
    float du = g_dinv[row];
    if (lane == 0) {
        float rs = du * (du + s);
        g_rowsum[row] = rs;
        atomicAdd(&g_acc[2], (double)rs);
    }
    float h0a = g_h0[row * Hh + lane];
    float h0b = g_h0[row * Hh + lane + 32];
    g_hsA[row * Hh + lane]      = __float2half_rn(du * h0a);
    g_hsA[row * Hh + lane + 32] = __float2half_rn(du * h0b);
}

// ---- shared gather helper: 16 threads/row, uint2 fp16, MLP-4 (round-8 proven) ----
__device__ __forceinline__ float4 gather_row(const uint2* hs2, int row, int j) {
    float2 f0, f1;
    {
        uint2 s0 = __ldg(&hs2[row * 16 + j]);
        f0 = __half22float2(*(__half2*)&s0.x);
        f1 = __half22float2(*(__half2*)&s0.y);
    }
    float ax = f0.x, ay = f0.y, az = f1.x, aw = f1.y;
    float bx = 0.f, by = 0.f, bz = 0.f, bw = 0.f;
    float cx = 0.f, cy = 0.f, cz = 0.f, cw = 0.f;
    float ex_ = 0.f, ey_ = 0.f, ez_ = 0.f, ew_ = 0.f;
    int deg = g_deg[row];
    const int* ci = g_colidx + row * MAXDEG;
    int e = 0;
    #pragma unroll 1
    for (; e + 4 <= deg; e += 4) {
        uint2 u0 = __ldg(&hs2[__ldg(&ci[e + 0]) * 16 + j]);
        uint2 u1 = __ldg(&hs2[__ldg(&ci[e + 1]) * 16 + j]);
        uint2 u2 = __ldg(&hs2[__ldg(&ci[e + 2]) * 16 + j]);
        uint2 u3 = __ldg(&hs2[__ldg(&ci[e + 3]) * 16 + j]);
        float2 g;
        g = __half22float2(*(__half2*)&u0.x); ax += g.x; ay += g.y;
        g = __half22float2(*(__half2*)&u0.y); az += g.x; aw += g.y;
        g = __half22float2(*(__half2*)&u1.x); bx += g.x; by += g.y;
        g = __half22float2(*(__half2*)&u1.y); bz += g.x; bw += g.y;
        g = __half22float2(*(__half2*)&u2.x); cx += g.x; cy += g.y;
        g = __half22float2(*(__half2*)&u2.y); cz += g.x; cw += g.y;
        g = __half22float2(*(__half2*)&u3.x); ex_ += g.x; ey_ += g.y;
        g = __half22float2(*(__half2*)&u3.y); ez_ += g.x; ew_ += g.y;
    }
    for (; e < deg; e++) {
        uint2 u0 = __ldg(&hs2[__ldg(&ci[e]) * 16 + j]);
        float2 g;
        g = __half22float2(*(__half2*)&u0.x); ax += g.x; ay += g.y;
        g = __half22float2(*(__half2*)&u0.y); az += g.x; aw += g.y;
    }
    float4 o;
    o.x = ax + bx + cx + ex_;
    o.y = ay + by + cy + ey_;
    o.z = az + bz + cz + ez_;
    o.w = aw + bw + cw + ew_;
    return o;
}

// ======= LN layers: 16 rows/block, 16 thr/row, grid = Nn/16 =======
__global__ __launch_bounds__(256) void k_layer(const __half* __restrict__ hs_in,
                                               __half* __restrict__ hs_out,
                                               const float* __restrict__ Wc,
                                               const float* __restrict__ lng,
                                               const float* __restrict__ lnb,
                                               float beta) {
    __shared__ float sW[Hh * Hh];
    __shared__ float sHm[16][Hh + 4];   // stride 272 B: 16B-aligned rows
    for (int i = threadIdx.x; i < Hh * Hh / 4; i += 256)
        ((float4*)sW)[i] = ((const float4*)Wc)[i];
    int r = threadIdx.x >> 4, j = threadIdx.x & 15;
    int row = blockIdx.x * 16 + r;
    float du = g_dinv[row];

    float4 a = gather_row((const uint2*)hs_in, row, j);

    float4 h0v = ((const float4*)g_h0)[row * 16 + j];
    float c1 = (1.f - ALPHAc) * du;
    float4 hm;
    hm.x = fmaf(c1, a.x, ALPHAc * h0v.x);
    hm.y = fmaf(c1, a.y, ALPHAc * h0v.y);
    hm.z = fmaf(c1, a.z, ALPHAc * h0v.z);
    hm.w = fmaf(c1, a.w, ALPHAc * h0v.w);
    *(float4*)&sHm[r][4 * j] = hm;
    __syncthreads();

    float4 t = make_float4(0.f, 0.f, 0.f, 0.f);
    const float* hmrow = sHm[r];
    #pragma unroll
    for (int k = 0; k < Hh; k++) {
        float hk = hmrow[k];
        float4 w = *(const float4*)&sW[k * Hh + 4 * j];
        t.x = fmaf(hk, w.x, t.x);
        t.y = fmaf(hk, w.y, t.y);
        t.z = fmaf(hk, w.z, t.z);
        t.w = fmaf(hk, w.w, t.w);
    }
    float4 v;
    v.x = fmaf(beta, t.x - hm.x, hm.x);
    v.y = fmaf(beta, t.y - hm.y, hm.y);
    v.z = fmaf(beta, t.z - hm.z, hm.z);
    v.w = fmaf(beta, t.w - hm.w, hm.w);

    // ReLU + LN
    v.x = fmaxf(v.x, 0.f); v.y = fmaxf(v.y, 0.f);
    v.z = fmaxf(v.z, 0.f); v.w = fmaxf(v.w, 0.f);
    float s = v.x + v.y + v.z + v.w;
    #pragma unroll
    for (int d = 8; d; d >>= 1) s += __shfl_xor_sync(0xffffffffu, s, d);
    float mu = s * (1.f / 64.f);
    float dx = v.x - mu, dy = v.y - mu, dz = v.z - mu, dw = v.w - mu;
    float q = dx * dx + dy * dy + dz * dz + dw * dw;
    #pragma unroll
    for (int d = 8; d; d >>= 1) q += __shfl_xor_sync(0xffffffffu, q, d);
    float rstd = rsqrtf(q * (1.f / 64.f) + LN_EPS);
    float4 gg = ((const float4*)lng)[j];
    float4 bb = ((const float4*)lnb)[j];
    v.x = fmaf(dx * rstd, gg.x, bb.x);
    v.y = fmaf(dy * rstd, gg.y, bb.y);
    v.z = fmaf(dz * rstd, gg.z, bb.z);
    v.w = fmaf(dw * rstd, gg.w, bb.w);
    __half2 p0 = __floats2half2_rn(du * v.x, du * v.y);
    __half2 p1 = __floats2half2_rn(du * v.z, du * v.w);
    uint2 o;
    o.x = *(unsigned*)&p0; o.y = *(unsigned*)&p1;
    ((uint2*)hs_out)[row * 16 + j] = o;
}

// ======= final layer fused with output head: GEMM + out + log_softmax + Dirichlet =======
__global__ __launch_bounds__(256) void k_layer_last(const __half* __restrict__ hs_in,
                                                    const float* __restrict__ Wc,
                                                    const float* __restrict__ Wout,
                                                    const float* __restrict__ bout,
                                                    float beta,
                                                    float* __restrict__ dout) {
    __shared__ float sW[Hh * Hh];
    __shared__ float sWo[Hh * Cc];
    __shared__ float sHm[16][Hh + 4];
    for (int i = threadIdx.x; i < Hh * Hh / 4; i += 256)
        ((float4*)sW)[i] = ((const float4*)Wc)[i];
    if (threadIdx.x < Hh * Cc / 4)
        ((float4*)sWo)[threadIdx.x] = ((const float4*)Wout)[threadIdx.x];
    int r = threadIdx.x >> 4, j = threadIdx.x & 15;
    int row = blockIdx.x * 16 + r;
    float du = g_dinv[row];

    float4 a = gather_row((const uint2*)hs_in, row, j);

    float4 h0v = ((const float4*)g_h0)[row * 16 + j];
    float c1 = (1.f - ALPHAc) * du;
    float4 hm;
    hm.x = fmaf(c1, a.x, ALPHAc * h0v.x);
    hm.y = fmaf(c1, a.y, ALPHAc * h0v.y);
    hm.z = fmaf(c1, a.z, ALPHAc * h0v.z);
    hm.w = fmaf(c1, a.w, ALPHAc * h0v.w);
    *(float4*)&sHm[r][4 * j] = hm;
    __syncthreads();

    float4 t = make_float4(0.f, 0.f, 0.f, 0.f);
    const float* hmrow = sHm[r];
    #pragma unroll
    for (int k = 0; k < Hh; k++) {
        float hk = hmrow[k];
        float4 w = *(const float4*)&sW[k * Hh + 4 * j];
        t.x = fmaf(hk, w.x, t.x);
        t.y = fmaf(hk, w.y, t.y);
        t.z = fmaf(hk, w.z, t.z);
        t.w = fmaf(hk, w.w, t.w);
    }
    float4 v;
    v.x = fmaf(beta, t.x - hm.x, hm.x);
    v.y = fmaf(beta, t.y - hm.y, hm.y);
    v.z = fmaf(beta, t.z - hm.z, hm.z);
    v.w = fmaf(beta, t.w - hm.w, hm.w);

    __syncwarp();
    *(float4*)&sHm[r][4 * j] = v;
    __syncwarp();

    // output head: thread j = class j
    const float* vr = sHm[r];
    float o = bout[j];
    #pragma unroll
    for (int k = 0; k < Hh; k++) o = fmaf(vr[k], sWo[k * Cc + j], o);
    dout[row * Cc + j] = o;
    float m = o;
    #pragma unroll
    for (int d = 1; d < 16; d <<= 1) m = fmaxf(m, __shfl_xor_sync(0xffffffffu, m, d));
    float ex = expf(o - m);
    float se = ex;
    #pragma unroll
    for (int d = 1; d < 16; d <<= 1) se += __shfl_xor_sync(0xffffffffu, se, d);
    dout[Nn * Cc + row * Cc + j] = o - m - logf(se);

    float gv = fmaxf(o, 0.f) * rsqrtf((float)g_deg[row] + 2.0f);
    g_gm[row * Cc + j] = gv;
    g_gs[row * Cc + j] = __float2half_rn(du * gv);
    float s = gv * gv;
    #pragma unroll
    for (int d = 1; d < 16; d <<= 1) s += __shfl_xor_sync(0xffffffffu, s, d);
    if (j == 0) atomicAdd(&g_acc[0], (double)(g_rowsum[row] * s));
}

// ---- term2 = sum_u (W@g)_u . g_u   (8 threads/row, fp16 gather) ----
__global__ void k_wg() {
    int row = blockIdx.x * 32 + (threadIdx.x >> 3);
    int q = threadIdx.x & 7;
    const unsigned* gs2 = (const unsigned*)g_gs;
    float ax, ay;
    {
        float2 f = __half22float2(*(const __half2*)&gs2[row * 8 + q]);
        ax = f.x; ay = f.y;
    }
    float bx = 0.f, by = 0.f, cx = 0.f, cy = 0.f, dx = 0.f, dy = 0.f;
    int deg = g_deg[row];
    const int* ci = g_colidx + row * MAXDEG;
    int e = 0;
    #pragma unroll 1
    for (; e + 4 <= deg; e += 4) {
        unsigned u0 = __ldg(&gs2[__ldg(&ci[e])     * 8 + q]);
        unsigned u1 = __ldg(&gs2[__ldg(&ci[e + 1]) * 8 + q]);
        unsigned u2 = __ldg(&gs2[__ldg(&ci[e + 2]) * 8 + q]);
        unsigned u3 = __ldg(&gs2[__ldg(&ci[e + 3]) * 8 + q]);
        float2 f;
        f = __half22float2(*(__half2*)&u0); ax += f.x; ay += f.y;
        f = __half22float2(*(__half2*)&u1); bx += f.x; by += f.y;
        f = __half22float2(*(__half2*)&u2); cx += f.x; cy += f.y;
        f = __half22float2(*(__half2*)&u3); dx += f.x; dy += f.y;
    }
    for (; e < deg; e++) {
        float2 f = __half22float2(*(const __half2*)&gs2[__ldg(&ci[e]) * 8 + q]);
        ax += f.x; ay += f.y;
    }
    ax += bx + cx + dx; ay += by + cy + dy;
    float2 gu = ((const float2*)g_gm)[row * 8 + q];
    float dot = ax * gu.x + ay * gu.y;
    dot += __shfl_xor_sync(0xffffffffu, dot, 1);
    dot += __shfl_xor_sync(0xffffffffu, dot, 2);
    dot += __shfl_xor_sync(0xffffffffu, dot, 4);
    if (q == 0) atomicAdd(&g_acc[1], (double)(g_dinv[row] * dot));
}

__global__ void k_fin(float* __restrict__ dout) {
    dout[2 * Nn * Cc] = (float)((g_acc[0] - g_acc[1]) / g_acc[2]);
}

// ---------------- launch ----------------
extern "C" void kernel_launch(void* const* d_in, const int* in_sizes, int n_in,
                              void* d_out, int out_size) {
    const float* x    = (const float*)d_in[0];
    const float* adj  = (const float*)d_in[1];
    const float* Win  = (const float*)d_in[2];
    const float* bin  = (const float*)d_in[3];
    const float* Wcv  = (const float*)d_in[4];
    const float* lng  = (const float*)d_in[5];
    const float* lnb  = (const float*)d_in[6];
    const float* Wout = (const float*)d_in[7];
    const float* bout = (const float*)d_in[8];
    float* out = (float*)d_out;

    k_front<<<GEMM_BLOCKS + CSR_BLOCKS, 256>>>(adj, x, Win, bin);
    k_mid<<<Nn / 8, 256>>>();

    void* hsA_p = nullptr; void* hsB_p = nullptr;
    cudaGetSymbolAddress(&hsA_p, g_hsA);
    cudaGetSymbolAddress(&hsB_p, g_hsB);
    __half* hsA = (__half*)hsA_p;
    __half* hsB = (__half*)hsB_p;

    const float betas[4] = {0.26236426446749106f, 0.13976194237515863f,
                            0.09531017980432486f, 0.07232066157962608f};
    k_layer<<<Nn / 16, 256>>>(hsA, hsB, Wcv + 0 * Hh * Hh, lng + 0 * Hh, lnb + 0 * Hh, betas[0]);
    k_layer<<<Nn / 16, 256>>>(hsB, hsA, Wcv + 1 * Hh * Hh, lng + 1 * Hh, lnb + 1 * Hh, betas[1]);
    k_layer<<<Nn / 16, 256>>>(hsA, hsB, Wcv + 2 * Hh * Hh, lng + 2 * Hh, lnb + 2 * Hh, betas[2]);
    k_layer_last<<<Nn / 16, 256>>>(hsB, Wcv + 3 * Hh * Hh, Wout, bout, betas[3], out);

    k_wg<<<Nn / 32, 256>>>();
    k_fin<<<1, 1>>>(out);
}